// round 2
// baseline (speedup 1.0000x reference)
#include <cuda_runtime.h>

#define S        2048   // NUM_SLICE
#define INCH     2048
#define H        100
#define G4       400    // 4*H gate rows
#define ITERLIM  128

// scratch for x_gates [S][G4]
__device__ float g_xg[S * G4];

// ---------------- f32x2 packed-FMA helpers (Blackwell) ----------------
__device__ __forceinline__ unsigned long long pk2(float lo, float hi) {
    unsigned long long r;
    asm("mov.b64 %0, {%1,%2};" : "=l"(r) : "f"(lo), "f"(hi));
    return r;
}
__device__ __forceinline__ float2 upk2(unsigned long long v) {
    float2 f;
    asm("mov.b64 {%0,%1}, %2;" : "=f"(f.x), "=f"(f.y) : "l"(v));
    return f;
}
__device__ __forceinline__ unsigned long long ffma2(unsigned long long a,
                                                    unsigned long long b,
                                                    unsigned long long c) {
    unsigned long long d;
    asm("fma.rn.f32x2 %0, %1, %2, %3;" : "=l"(d) : "l"(a), "l"(b), "l"(c));
    return d;
}

// ---------------- activations (accurate-ish: __expf = 2 ulp) ----------------
__device__ __forceinline__ float sigf(float x) {
    return __fdividef(1.0f, 1.0f + __expf(-x));
}
__device__ __forceinline__ float tanhf_(float x) {
    // tanh(x) = 2*sigmoid(2x) - 1 ; saturates correctly for |x| large
    return __fdividef(2.0f, 1.0f + __expf(-2.0f * x)) - 1.0f;
}

// =====================================================================
// Kernel 1: x_gates[s][r] = sum_k x[k*S + s] * Wih[r*INCH + k] + bih[r]
// Tiled GEMM, f32x2 packed accumulation over s-pairs.
// =====================================================================
#define BM 64
#define BN 64
#define BK 16

__global__ __launch_bounds__(256) void gemm_xgates(const float* __restrict__ x,
                                                   const float* __restrict__ Wih,
                                                   const float* __restrict__ bih) {
    __shared__ float xs[BK][BM];
    __shared__ float ws[BN][BK];

    const int tid = threadIdx.x;
    const int s0 = blockIdx.x * BM;
    const int r0 = blockIdx.y * BN;
    const int tx = tid & 15;   // 16 groups over s (4 s each)
    const int ty = tid >> 4;   // 16 groups over r (4 r each)

    unsigned long long a0[4], a1[4];
#pragma unroll
    for (int j = 0; j < 4; j++) { a0[j] = 0ull; a1[j] = 0ull; }

    for (int k0 = 0; k0 < INCH; k0 += BK) {
#pragma unroll
        for (int i = 0; i < 4; i++) {
            int idx = tid + i * 256;
            int kk = idx >> 6, si = idx & 63;
            xs[kk][si] = x[(k0 + kk) * S + s0 + si];
        }
#pragma unroll
        for (int i = 0; i < 4; i++) {
            int idx = tid + i * 256;
            int kk = idx & 15, rj = idx >> 4;
            int r = r0 + rj;
            ws[rj][kk] = (r < G4) ? Wih[r * INCH + k0 + kk] : 0.0f;
        }
        __syncthreads();

#pragma unroll
        for (int kk = 0; kk < BK; kk++) {
            float4 xv = *(const float4*)&xs[kk][tx * 4];
            unsigned long long xlo = pk2(xv.x, xv.y);
            unsigned long long xhi = pk2(xv.z, xv.w);
#pragma unroll
            for (int jj = 0; jj < 4; jj++) {
                float wv = ws[ty * 4 + jj][kk];
                unsigned long long wd = pk2(wv, wv);
                a0[jj] = ffma2(xlo, wd, a0[jj]);
                a1[jj] = ffma2(xhi, wd, a1[jj]);
            }
        }
        __syncthreads();
    }

#pragma unroll
    for (int jj = 0; jj < 4; jj++) {
        int r = r0 + ty * 4 + jj;
        if (r < G4) {
            float bb = bih[r];
            float2 v0 = upk2(a0[jj]);
            float2 v1 = upk2(a1[jj]);
            int sb = s0 + tx * 4;
            g_xg[(sb + 0) * G4 + r] = v0.x + bb;
            g_xg[(sb + 1) * G4 + r] = v0.y + bb;
            g_xg[(sb + 2) * G4 + r] = v1.x + bb;
            g_xg[(sb + 3) * G4 + r] = v1.y + bb;
        }
    }
}

// =====================================================================
// Kernel 2: persistent single-CTA LSTM scan (phase 1 + phase 2).
// 416 threads = 104 quads. Quad rg (element), lane kc = k-chunk (4-way).
// Each thread holds W_hh for gate rows {rg, rg+100, rg+200, rg+300},
// k in [kc*28, kc*28+28) (h padded to 112), as 56 packed f32x2 registers.
// =====================================================================

// One LSTM step over slice index TSLICE. Reads hs[buf], writes hs[buf^1],
// one __syncthreads, flips buf.
#define LSTM_STEP(TSLICE)                                                         \
    {                                                                             \
        const ulonglong2* hc = &hs[buf][0];                                       \
        float xgv = act ? g_xg[(TSLICE) * G4 + rg + kc * H] : 0.0f;               \
        unsigned long long ac0 = 0ull, ac1 = 0ull, ac2 = 0ull, ac3 = 0ull;        \
        _Pragma("unroll")                                                         \
        for (int j = 0; j < 7; j++) {                                             \
            ulonglong2 h2 = hc[kc * 7 + j];                                       \
            ac0 = ffma2(w0[2 * j], h2.x, ac0);                                    \
            ac1 = ffma2(w1[2 * j], h2.x, ac1);                                    \
            ac2 = ffma2(w2[2 * j], h2.x, ac2);                                    \
            ac3 = ffma2(w3[2 * j], h2.x, ac3);                                    \
            ac0 = ffma2(w0[2 * j + 1], h2.y, ac0);                                \
            ac1 = ffma2(w1[2 * j + 1], h2.y, ac1);                                \
            ac2 = ffma2(w2[2 * j + 1], h2.y, ac2);                                \
            ac3 = ffma2(w3[2 * j + 1], h2.y, ac3);                                \
        }                                                                         \
        float2 f0 = upk2(ac0), f1 = upk2(ac1), f2 = upk2(ac2), f3 = upk2(ac3);    \
        float z0 = f0.x + f0.y;                                                   \
        float z1 = f1.x + f1.y;                                                   \
        float z2 = f2.x + f2.y;                                                   \
        float z3 = f3.x + f3.y;                                                   \
        float addv = xgv + bhhv;                                                  \
        if (kc == 0) z0 += addv;                                                  \
        else if (kc == 1) z1 += addv;                                             \
        else if (kc == 2) z2 += addv;                                             \
        else z3 += addv;                                                          \
        z0 += __shfl_xor_sync(0xffffffffu, z0, 1);                                \
        z0 += __shfl_xor_sync(0xffffffffu, z0, 2);                                \
        z1 += __shfl_xor_sync(0xffffffffu, z1, 1);                                \
        z1 += __shfl_xor_sync(0xffffffffu, z1, 2);                                \
        z2 += __shfl_xor_sync(0xffffffffu, z2, 1);                                \
        z2 += __shfl_xor_sync(0xffffffffu, z2, 2);                                \
        z3 += __shfl_xor_sync(0xffffffffu, z3, 1);                                \
        z3 += __shfl_xor_sync(0xffffffffu, z3, 2);                                \
        /* distribute nonlinearities one per lane */                              \
        float nl;                                                                 \
        if (kc == 0) nl = sigf(z0);       /* sig(i)  */                           \
        else if (kc == 1) nl = sigf(z1);  /* sig(f)  */                           \
        else if (kc == 2) nl = tanhf_(z2);/* tanh(g) */                           \
        else nl = sigf(z3);               /* sig(o)  */                           \
        int lane = tid & 31;                                                      \
        int qb = lane & ~3;                                                       \
        float nlf = __shfl_sync(0xffffffffu, nl, qb + 1);                         \
        float nlg = __shfl_sync(0xffffffffu, nl, qb + 2);                         \
        float nlo = __shfl_sync(0xffffffffu, nl, qb + 3);                         \
        if (kc == 0 && act) {                                                     \
            float cn = nlf * creg + nl * nlg;                                     \
            creg = cn;                                                            \
            float hn = nlo * tanhf_(cn);                                          \
            ((float*)&hs[buf ^ 1][0])[rg] = hn;                                   \
        }                                                                         \
        __syncthreads();                                                          \
        buf ^= 1;                                                                 \
    }

__global__ __launch_bounds__(416, 1) void lstm_scan(const float* __restrict__ Whh,
                                                    const float* __restrict__ bhh,
                                                    const float* __restrict__ Wfc,
                                                    const float* __restrict__ bfc,
                                                    float* __restrict__ out) {
    // h double buffer: 2 x 112 floats packed as ulonglong2 (f32x2 pairs)
    __shared__ ulonglong2 hs[2][28];
    __shared__ float swfc[3 * H];
    __shared__ float sbfc[3];
    __shared__ int s_idx;
    __shared__ int s_done;

    const int tid = threadIdx.x;
    const int rg = tid >> 2;   // 0..103 (element index; active < 100)
    const int kc = tid & 3;    // k-chunk
    const bool act = (rg < H);

    // --- init shared ---
    for (int i = tid; i < 2 * 28 * 4; i += 416) ((float*)hs)[i] = 0.0f;
    for (int i = tid; i < 3 * H; i += 416) swfc[i] = Wfc[i];
    if (tid < 3) sbfc[tid] = bfc[tid];
    if (tid == 0) { s_idx = S / 2; s_done = 0; }

    // --- load W_hh rows into registers (packed f32x2 along k) ---
    unsigned long long w0[14], w1[14], w2[14], w3[14];
    {
        const int r0 = rg, r1 = rg + H, r2 = rg + 2 * H, r3 = rg + 3 * H;
#pragma unroll
        for (int j = 0; j < 14; j++) {
            int k0 = kc * 28 + 2 * j;
            float a0 = 0, b0 = 0, a1 = 0, b1 = 0, a2 = 0, b2 = 0, a3 = 0, b3 = 0;
            if (act && k0 < H) {
                a0 = Whh[r0 * H + k0]; a1 = Whh[r1 * H + k0];
                a2 = Whh[r2 * H + k0]; a3 = Whh[r3 * H + k0];
            }
            if (act && k0 + 1 < H) {
                b0 = Whh[r0 * H + k0 + 1]; b1 = Whh[r1 * H + k0 + 1];
                b2 = Whh[r2 * H + k0 + 1]; b3 = Whh[r3 * H + k0 + 1];
            }
            w0[j] = pk2(a0, b0);
            w1[j] = pk2(a1, b1);
            w2[j] = pk2(a2, b2);
            w3[j] = pk2(a3, b3);
        }
    }
    float bhhv = act ? bhh[rg + kc * H] : 0.0f;
    float creg = 0.0f;

    __syncthreads();

    int buf = 0;

    // ---------------- phase 1: full sequential pass ----------------
    for (int t = 0; t < S; t++) {
        LSTM_STEP(t)
    }

    // ---------------- phase 2: data-dependent scan ----------------
    float o0 = 0.0f, o1 = 0.0f;  // live in thread 0
    int consec = 0;              // live in thread 0

    for (int it = 0; it < ITERLIM; it++) {
        const int t = s_idx;  // read after barrier of previous iteration
        LSTM_STEP(t)
        // new h is in hs[buf] now (buf was flipped inside LSTM_STEP)

        if (tid < 32) {
            const float* hv = (const float*)&hs[buf][0];
            float p0 = 0.0f, p1 = 0.0f, p2 = 0.0f;
            for (int k = tid; k < H; k += 32) {
                float h = hv[k];
                p0 += swfc[k] * h;
                p1 += swfc[H + k] * h;
                p2 += swfc[2 * H + k] * h;
            }
#pragma unroll
            for (int off = 16; off; off >>= 1) {
                p0 += __shfl_down_sync(0xffffffffu, p0, off);
                p1 += __shfl_down_sync(0xffffffffu, p1, off);
                p2 += __shfl_down_sync(0xffffffffu, p2, off);
            }
            if (tid == 0) {
                p0 += sbfc[0]; p1 += sbfc[1]; p2 += sbfc[2];
                o0 = p0;
                o1 = p1;
                consec = (p1 > 0.0f) ? (consec + 1) : 0;
                if (consec > 3) s_done = 1;
                s_idx = (p2 > 0.0f) ? ((t + 1) & (S - 1)) : ((t - 1) & (S - 1));
            }
        }
        __syncthreads();
        if (s_done) break;
    }

    if (tid == 0) {
        out[0] = o0;
        out[1] = o1;
    }
}

// =====================================================================
// launch
// =====================================================================
extern "C" void kernel_launch(void* const* d_in, const int* in_sizes, int n_in,
                              void* d_out, int out_size) {
    const float* x   = (const float*)d_in[0];
    const float* Wih = (const float*)d_in[1];
    const float* Whh = (const float*)d_in[2];
    const float* bih = (const float*)d_in[3];
    const float* bhh = (const float*)d_in[4];
    const float* Wfc = (const float*)d_in[5];
    const float* bfc = (const float*)d_in[6];
    float* out = (float*)d_out;

    dim3 grid(S / BM, (G4 + BN - 1) / BN);
    gemm_xgates<<<grid, 256>>>(x, Wih, bih);
    lstm_scan<<<1, 416>>>(Whh, bhh, Wfc, bfc, out);
}

// round 3
// speedup vs baseline: 2.0192x; 2.0192x over previous
#include <cuda_runtime.h>

#define S        2048   // NUM_SLICE
#define INCH     2048
#define H        100
#define G4       400    // 4*H gate rows
#define ITERLIM  128

// scratch for x_gates [S][G4]
__device__ float g_xg[S * G4];

// ---------------- f32x2 packed-FMA helpers (Blackwell) ----------------
__device__ __forceinline__ unsigned long long pk2(float lo, float hi) {
    unsigned long long r;
    asm("mov.b64 %0, {%1,%2};" : "=l"(r) : "f"(lo), "f"(hi));
    return r;
}
__device__ __forceinline__ float2 upk2(unsigned long long v) {
    float2 f;
    asm("mov.b64 {%0,%1}, %2;" : "=f"(f.x), "=f"(f.y) : "l"(v));
    return f;
}
__device__ __forceinline__ unsigned long long ffma2(unsigned long long a,
                                                    unsigned long long b,
                                                    unsigned long long c) {
    unsigned long long d;
    asm("fma.rn.f32x2 %0, %1, %2, %3;" : "=l"(d) : "l"(a), "l"(b), "l"(c));
    return d;
}

// ---------------- activations (__expf ~2 ulp) ----------------
__device__ __forceinline__ float sigf(float x) {
    return __fdividef(1.0f, 1.0f + __expf(-x));
}
__device__ __forceinline__ float tanhf_(float x) {
    return __fdividef(2.0f, 1.0f + __expf(-2.0f * x)) - 1.0f;
}

// =====================================================================
// Kernel 1: x_gates[s][r] = sum_k x[k*S + s] * Wih[r*INCH + k] + bih[r]
// (unchanged from round 1 — measured scan dominates)
// =====================================================================
#define BM 64
#define BN 64
#define BK 16

__global__ __launch_bounds__(256) void gemm_xgates(const float* __restrict__ x,
                                                   const float* __restrict__ Wih,
                                                   const float* __restrict__ bih) {
    __shared__ float xs[BK][BM];
    __shared__ float ws[BN][BK];

    const int tid = threadIdx.x;
    const int s0 = blockIdx.x * BM;
    const int r0 = blockIdx.y * BN;
    const int tx = tid & 15;
    const int ty = tid >> 4;

    unsigned long long a0[4], a1[4];
#pragma unroll
    for (int j = 0; j < 4; j++) { a0[j] = 0ull; a1[j] = 0ull; }

    for (int k0 = 0; k0 < INCH; k0 += BK) {
#pragma unroll
        for (int i = 0; i < 4; i++) {
            int idx = tid + i * 256;
            int kk = idx >> 6, si = idx & 63;
            xs[kk][si] = x[(k0 + kk) * S + s0 + si];
        }
#pragma unroll
        for (int i = 0; i < 4; i++) {
            int idx = tid + i * 256;
            int kk = idx & 15, rj = idx >> 4;
            int r = r0 + rj;
            ws[rj][kk] = (r < G4) ? Wih[r * INCH + k0 + kk] : 0.0f;
        }
        __syncthreads();

#pragma unroll
        for (int kk = 0; kk < BK; kk++) {
            float4 xv = *(const float4*)&xs[kk][tx * 4];
            unsigned long long xlo = pk2(xv.x, xv.y);
            unsigned long long xhi = pk2(xv.z, xv.w);
#pragma unroll
            for (int jj = 0; jj < 4; jj++) {
                float wv = ws[ty * 4 + jj][kk];
                unsigned long long wd = pk2(wv, wv);
                a0[jj] = ffma2(xlo, wd, a0[jj]);
                a1[jj] = ffma2(xhi, wd, a1[jj]);
            }
        }
        __syncthreads();
    }

#pragma unroll
    for (int jj = 0; jj < 4; jj++) {
        int r = r0 + ty * 4 + jj;
        if (r < G4) {
            float bb = bih[r];
            float2 v0 = upk2(a0[jj]);
            float2 v1 = upk2(a1[jj]);
            int sb = s0 + tx * 4;
            g_xg[(sb + 0) * G4 + r] = v0.x + bb;
            g_xg[(sb + 1) * G4 + r] = v0.y + bb;
            g_xg[(sb + 2) * G4 + r] = v1.x + bb;
            g_xg[(sb + 3) * G4 + r] = v1.y + bb;
        }
    }
}

// =====================================================================
// Kernel 2: persistent single-CTA LSTM scan.
// 256 threads = 8 warps = 128 (rg) pairs x 2 (p = k-half).
// Thread (rg, p) holds W_hh rows {rg, rg+100, rg+200, rg+300} for
// k in [50p, 50p+50): 200 weight registers (fits 255-reg cap, no spill).
// Lane p ends owning gates {p, p+2} after one butterfly round.
// =====================================================================

// One LSTM step. Uses xg values XGA (gate p) / XGB (gate p+2) already in
// registers. Reads hs[buf], writes hs[buf^1], 1 barrier, flips buf.
#define LSTM_STEP(XGA, XGB)                                                       \
    {                                                                             \
        const unsigned long long* hc =                                            \
            (const unsigned long long*)&hs[buf][0] + 25 * p;                      \
        unsigned long long ac0 = 0ull, ac1 = 0ull, ac2 = 0ull, ac3 = 0ull;        \
        _Pragma("unroll")                                                         \
        for (int j = 0; j < 25; j++) {                                            \
            unsigned long long h2 = hc[j];                                        \
            ac0 = ffma2(w0[j], h2, ac0);                                          \
            ac1 = ffma2(w1[j], h2, ac1);                                          \
            ac2 = ffma2(w2[j], h2, ac2);                                          \
            ac3 = ffma2(w3[j], h2, ac3);                                          \
        }                                                                         \
        float2 f0 = upk2(ac0), f1 = upk2(ac1), f2 = upk2(ac2), f3 = upk2(ac3);    \
        float z0 = f0.x + f0.y;                                                   \
        float z1 = f1.x + f1.y;                                                   \
        float z2 = f2.x + f2.y;                                                   \
        float z3 = f3.x + f3.y;                                                   \
        /* butterfly: lane p keeps gates {p, p+2}, exchanges the others */        \
        float zA = p ? z1 : z0;                                                   \
        float zB = p ? z3 : z2;                                                   \
        float sA = p ? z0 : z1;                                                   \
        float sB = p ? z2 : z3;                                                   \
        zA += __shfl_xor_sync(0xffffffffu, sA, 1);                                \
        zB += __shfl_xor_sync(0xffffffffu, sB, 1);                                \
        zA += (XGA) + bA;                                                         \
        zB += (XGB) + bB;                                                         \
        /* lane0: nlA=sig(i), nlB=tanh(g); lane1: nlA=sig(f), nlB=sig(o) */       \
        float nlA = sigf(zA);                                                     \
        float aB  = p ? -zB : -(zB + zB);                                         \
        float eB  = __expf(aB);                                                   \
        float sB2 = __fdividef(1.0f, 1.0f + eB);                                  \
        float nlB = p ? sB2 : (sB2 + sB2 - 1.0f);                                 \
        /* gather partner's pair */                                               \
        float gA = __shfl_xor_sync(0xffffffffu, nlA, 1);                          \
        float gB = __shfl_xor_sync(0xffffffffu, nlB, 1);                          \
        if (p == 0 && act) {                                                      \
            /* gA = sig(f), gB = sig(o), nlA = sig(i), nlB = tanh(g) */           \
            float cn = gA * creg + nlA * nlB;                                     \
            creg = cn;                                                            \
            float hn = gB * tanhf_(cn);                                           \
            hs[buf ^ 1][rg] = hn;                                                 \
        }                                                                         \
        __syncthreads();                                                          \
        buf ^= 1;                                                                 \
    }

__global__ __launch_bounds__(256, 1) void lstm_scan(const float* __restrict__ Whh,
                                                    const float* __restrict__ bhh,
                                                    const float* __restrict__ Wfc,
                                                    const float* __restrict__ bfc,
                                                    float* __restrict__ out) {
    __shared__ __align__(16) float hs[2][H];   // double-buffered h
    __shared__ float swfc[3 * H];
    __shared__ float sbfc[3];
    __shared__ int s_idx;
    __shared__ int s_done;

    const int tid = threadIdx.x;
    const int rg = tid >> 1;   // 0..127 (active < 100)
    const int p = tid & 1;     // k-half
    const bool act = (rg < H);

    // gate row indices this lane owns post-reduce: gate p and gate p+2
    const int rA = p * H + rg;         // gate p
    const int rB = (p + 2) * H + rg;   // gate p+2

    // --- init shared ---
    for (int i = tid; i < 2 * H; i += 256) ((float*)hs)[i] = 0.0f;
    for (int i = tid; i < 3 * H; i += 256) swfc[i] = Wfc[i];
    if (tid < 3) sbfc[tid] = bfc[tid];
    if (tid == 0) { s_idx = S / 2; s_done = 0; }

    // --- W_hh into registers: 4 gates x 25 f32x2 (k in [50p, 50p+50)) ---
    unsigned long long w0[25], w1[25], w2[25], w3[25];
    {
        const int r0 = rg, r1 = rg + H, r2 = rg + 2 * H, r3 = rg + 3 * H;
#pragma unroll
        for (int j = 0; j < 25; j++) {
            int k0 = 50 * p + 2 * j;
            float a0 = 0, b0 = 0, a1 = 0, b1 = 0, a2 = 0, b2 = 0, a3 = 0, b3 = 0;
            if (act) {
                a0 = Whh[r0 * H + k0]; b0 = Whh[r0 * H + k0 + 1];
                a1 = Whh[r1 * H + k0]; b1 = Whh[r1 * H + k0 + 1];
                a2 = Whh[r2 * H + k0]; b2 = Whh[r2 * H + k0 + 1];
                a3 = Whh[r3 * H + k0]; b3 = Whh[r3 * H + k0 + 1];
            }
            w0[j] = pk2(a0, b0);
            w1[j] = pk2(a1, b1);
            w2[j] = pk2(a2, b2);
            w3[j] = pk2(a3, b3);
        }
    }
    const float bA = act ? bhh[rA] : 0.0f;
    const float bB = act ? bhh[rB] : 0.0f;
    float creg = 0.0f;

    __syncthreads();

    int buf = 0;

    // ---------------- phase 1: sequential pass with xg prefetch ----------------
    float xgA = act ? g_xg[rA] : 0.0f;   // t = 0
    float xgB = act ? g_xg[rB] : 0.0f;
#pragma unroll 1
    for (int t = 0; t < S; t++) {
        // prefetch next step's xg (independent: overlaps the FMA block)
        float xgA_n = 0.0f, xgB_n = 0.0f;
        if (act && t + 1 < S) {
            xgA_n = g_xg[(t + 1) * G4 + rA];
            xgB_n = g_xg[(t + 1) * G4 + rB];
        }
        LSTM_STEP(xgA, xgB)
        xgA = xgA_n;
        xgB = xgB_n;
    }

    // ---------------- phase 2: data-dependent scan ----------------
    float o0 = 0.0f, o1 = 0.0f;  // thread 0
    int consec = 0;              // thread 0

    int t = S / 2;
    xgA = act ? g_xg[t * G4 + rA] : 0.0f;
    xgB = act ? g_xg[t * G4 + rB] : 0.0f;

#pragma unroll 1
    for (int it = 0; it < ITERLIM; it++) {
        const int tp = (t + 1) & (S - 1);
        const int tm = (t - 1) & (S - 1);
        // prefetch both candidate next slices (hides L2 latency)
        float pA = 0, pB = 0, mA = 0, mB = 0;
        if (act) {
            pA = g_xg[tp * G4 + rA];
            pB = g_xg[tp * G4 + rB];
            mA = g_xg[tm * G4 + rA];
            mB = g_xg[tm * G4 + rB];
        }

        LSTM_STEP(xgA, xgB)
        // new h is in hs[buf]

        if (tid < 32) {
            const float* hv = &hs[buf][0];
            float q0 = 0.0f, q1 = 0.0f, q2 = 0.0f;
            for (int k = tid; k < H; k += 32) {
                float h = hv[k];
                q0 += swfc[k] * h;
                q1 += swfc[H + k] * h;
                q2 += swfc[2 * H + k] * h;
            }
#pragma unroll
            for (int off = 16; off; off >>= 1) {
                q0 += __shfl_down_sync(0xffffffffu, q0, off);
                q1 += __shfl_down_sync(0xffffffffu, q1, off);
                q2 += __shfl_down_sync(0xffffffffu, q2, off);
            }
            if (tid == 0) {
                q0 += sbfc[0]; q1 += sbfc[1]; q2 += sbfc[2];
                o0 = q0;
                o1 = q1;
                consec = (q1 > 0.0f) ? (consec + 1) : 0;
                if (consec > 3) s_done = 1;
                s_idx = (q2 > 0.0f) ? tp : tm;
            }
        }
        __syncthreads();
        if (s_done) break;
        const int tn = s_idx;
        const bool fwd = (tn == tp);
        xgA = fwd ? pA : mA;
        xgB = fwd ? pB : mB;
        t = tn;
    }

    if (tid == 0) {
        out[0] = o0;
        out[1] = o1;
    }
}

// =====================================================================
// launch
// =====================================================================
extern "C" void kernel_launch(void* const* d_in, const int* in_sizes, int n_in,
                              void* d_out, int out_size) {
    const float* x   = (const float*)d_in[0];
    const float* Wih = (const float*)d_in[1];
    const float* Whh = (const float*)d_in[2];
    const float* bih = (const float*)d_in[3];
    const float* bhh = (const float*)d_in[4];
    const float* Wfc = (const float*)d_in[5];
    const float* bfc = (const float*)d_in[6];
    float* out = (float*)d_out;

    dim3 grid(S / BM, (G4 + BN - 1) / BN);
    gemm_xgates<<<grid, 256>>>(x, Wih, bih);
    lstm_scan<<<1, 256>>>(Whh, bhh, Wfc, bfc, out);
}